// round 7
// baseline (speedup 1.0000x reference)
#include <cuda_runtime.h>

// Problem constants
#define A_N 2048
#define D_N 64
#define F_N 12
#define K_N (A_N * F_N)   // 24576
#define C_N 66            // D + 2
#define GN  (F_N * D_N)   // 768 = columns of W-matrix view

// Split-K config for the big GEMM: 16 M-tiles x 9 K-splits = 144 CTAs (one wave on 148 SMs)
#define NSPLIT 9
#define KCHUNK 2736       // 8*2736 + 2688 = 24576, both multiples of BK=16

// ---------------------------------------------------------------------------
// Scratch (device globals only — no allocation allowed)
// ---------------------------------------------------------------------------
__device__ float g_G[2][D_N * GN];          // G[fi][d][f*64+o] = filt_fi[o][f][d]
__device__ float g_bt[2][A_N * D_N];        // bond term per filter (x-independent)
__device__ float g_W[K_N * D_N];            // W[k][o], k = n*12+f  (== x @ G, row-major 2048x768)
__device__ float g_xa[A_N * D_N];           // activation ping
__device__ float g_xb[A_N * D_N];           // activation pong
__device__ float g_part[NSPLIT][A_N * D_N]; // split-K partials

// ---------------------------------------------------------------------------
// Packed fp32x2 helpers (Blackwell: 2x fp32 FMA throughput; ptxas won't auto-fuse)
// ---------------------------------------------------------------------------
__device__ __forceinline__ unsigned long long pack2(float x, float y) {
    unsigned long long r;
    asm("mov.b64 %0, {%1, %2};" : "=l"(r) : "f"(x), "f"(y));
    return r;
}
__device__ __forceinline__ void unpack2(unsigned long long v, float &lo, float &hi) {
    asm("mov.b64 {%0, %1}, %2;" : "=f"(lo), "=f"(hi) : "l"(v));
}
__device__ __forceinline__ void ffma2(unsigned long long &acc, unsigned long long a,
                                      unsigned long long b) {
    asm("fma.rn.f32x2 %0, %1, %2, %0;" : "+l"(acc) : "l"(a), "l"(b));
}

// ---------------------------------------------------------------------------
// Prep: transpose filters into G  (G[fi][d*768 + f*64 + o] = filt[o*792 + f*66 + d])
// ---------------------------------------------------------------------------
__global__ void prep_g_kernel(const float* __restrict__ f0, const float* __restrict__ f1) {
    int i = blockIdx.x * blockDim.x + threadIdx.x;
    if (i >= 2 * D_N * GN) return;
    int fi = i / (D_N * GN);
    int r  = i % (D_N * GN);
    int d  = r / GN;
    int j  = r % GN;          // j = f*64 + o
    int f  = j >> 6;
    int o  = j & 63;
    const float* filt = fi ? f1 : f0;
    g_G[fi][r] = filt[(o * F_N + f) * C_N + d];
}

// Prep: bond term  bt[fi][a][o] = sum_f bond[a,f,0]*filt[o,f,64] + bond[a,f,1]*filt[o,f,65]
__global__ void prep_bt_kernel(const float* __restrict__ bond,
                               const float* __restrict__ f0,
                               const float* __restrict__ f1) {
    int i = blockIdx.x * blockDim.x + threadIdx.x;
    if (i >= 2 * A_N * D_N) return;
    int fi = i / (A_N * D_N);
    int r  = i % (A_N * D_N);
    int a  = r / D_N;
    int o  = r % D_N;
    const float* filt = fi ? f1 : f0;
    float s = 0.f;
#pragma unroll
    for (int f = 0; f < F_N; ++f) {
        s += bond[(a * F_N + f) * 2 + 0] * filt[(o * F_N + f) * C_N + 64];
        s += bond[(a * F_N + f) * 2 + 1] * filt[(o * F_N + f) * C_N + 65];
    }
    g_bt[fi][r] = s;
}

// ---------------------------------------------------------------------------
// W GEMM:  W(2048 x 768) = X(2048 x 64) @ G(64 x 768)
// Block: 64(M) x 128(N), 256 threads, full K=64 in smem. grid (32, 6).
// xsel: 0 -> g_xa, 1 -> g_xb, else external pointer.
// ---------------------------------------------------------------------------
__global__ void __launch_bounds__(256) wgemm_kernel(const float* __restrict__ xext,
                                                    int xsel, int fi) {
    const float* X = (xsel == 0) ? g_xa : (xsel == 1) ? g_xb : xext;
    const float* G = g_G[fi];

    __shared__ float xs[64][68];   // xs[k][m], padded
    __shared__ float gs[64][128];  // gs[k][n]

    int tid = threadIdx.x;
    int m0 = blockIdx.x * 64;
    int j0 = blockIdx.y * 128;

    // Load X tile (64 rows x 64 k), transpose into xs[k][m]
    for (int i = tid; i < 64 * 16; i += 256) {   // 1024 float4
        int row = i >> 4;
        int kq  = i & 15;
        float4 v = *(const float4*)&X[(size_t)(m0 + row) * D_N + kq * 4];
        xs[kq * 4 + 0][row] = v.x;
        xs[kq * 4 + 1][row] = v.y;
        xs[kq * 4 + 2][row] = v.z;
        xs[kq * 4 + 3][row] = v.w;
    }
    // Load G tile (64 x 128) directly
    for (int i = tid; i < 64 * 32; i += 256) {   // 2048 float4
        int d  = i >> 5;
        int cq = i & 31;
        *(float4*)&gs[d][cq * 4] = *(const float4*)&G[(size_t)d * GN + j0 + cq * 4];
    }
    __syncthreads();

    int tx = tid & 31;   // n: tx*4
    int ty = tid >> 5;   // m: ty*8 .. +7
    float acc[8][4];
#pragma unroll
    for (int im = 0; im < 8; ++im)
#pragma unroll
        for (int jn = 0; jn < 4; ++jn) acc[im][jn] = 0.f;

#pragma unroll 4
    for (int k = 0; k < 64; ++k) {
        float4 a0 = *(const float4*)&xs[k][ty * 8];
        float4 a1 = *(const float4*)&xs[k][ty * 8 + 4];
        float4 b  = *(const float4*)&gs[k][tx * 4];
        float av[8] = {a0.x, a0.y, a0.z, a0.w, a1.x, a1.y, a1.z, a1.w};
        float bv[4] = {b.x, b.y, b.z, b.w};
#pragma unroll
        for (int im = 0; im < 8; ++im)
#pragma unroll
            for (int jn = 0; jn < 4; ++jn) acc[im][jn] += av[im] * bv[jn];
    }

#pragma unroll
    for (int im = 0; im < 8; ++im) {
        size_t row = (size_t)(m0 + ty * 8 + im);
        *(float4*)&g_W[row * GN + j0 + tx * 4] =
            make_float4(acc[im][0], acc[im][1], acc[im][2], acc[im][3]);
    }
}

// ---------------------------------------------------------------------------
// Big GEMM (split-K):  part[s] += conn(2048 x 24576) @ W(24576 x 64)  for k-slice s
// BM=128, BN=64, BK=16, 256 threads, f32x2 packed FMAs. grid (16, 9).
// ---------------------------------------------------------------------------
__global__ void __launch_bounds__(256, 1) big_gemm_kernel(const float* __restrict__ conn) {
    __shared__ float As[16][132];   // As[kk][m], padded
    __shared__ float Bs[16][64];    // Bs[kk][n]

    int tid   = threadIdx.x;
    int mbase = blockIdx.x * 128;
    int s     = blockIdx.y;
    int k0    = s * KCHUNK;
    int klen  = min(KCHUNK, K_N - k0);
    int niter = klen >> 4;

    // compute-thread mapping: 16x16 threads, thread tile 8m x 4n
    int tx = tid & 15, ty = tid >> 4;
    const int mo0 = ty * 4;
    const int mo1 = ty * 4 + 64;
    const int no  = tx * 4;

    // acc[mpair][n]: mpair 0=(mo0,mo0+1) 1=(mo0+2,mo0+3) 2=(mo1,mo1+1) 3=(mo1+2,mo1+3)
    unsigned long long acc[4][4];
#pragma unroll
    for (int p = 0; p < 4; ++p)
#pragma unroll
        for (int n = 0; n < 4; ++n) acc[p][n] = 0ULL;

    // A loader mapping: element i in [0,512) float4s: row=i>>2, kseg=i&3
    const int arow = tid >> 2;
    const int kcol = (tid & 3) * 4;
    const float* aptr0 = conn + (size_t)(mbase + arow) * K_N + k0 + kcol;
    const float* aptr1 = aptr0 + (size_t)64 * K_N;

    // B loader mapping: kkb in 0..3, ob in 0..63; covers kk = kkb + 4p
    const int kkb = tid >> 6;
    const int ob  = tid & 63;

    float4 aR0 = *(const float4*)(aptr0);
    float4 aR1 = *(const float4*)(aptr1);
    float  bR[4];
#pragma unroll
    for (int p = 0; p < 4; ++p) bR[p] = g_W[(size_t)(k0 + kkb + p * 4) * D_N + ob];

    for (int it = 0; it < niter; ++it) {
        // stage -> smem
        As[kcol + 0][arow]      = aR0.x;
        As[kcol + 1][arow]      = aR0.y;
        As[kcol + 2][arow]      = aR0.z;
        As[kcol + 3][arow]      = aR0.w;
        As[kcol + 0][arow + 64] = aR1.x;
        As[kcol + 1][arow + 64] = aR1.y;
        As[kcol + 2][arow + 64] = aR1.z;
        As[kcol + 3][arow + 64] = aR1.w;
#pragma unroll
        for (int p = 0; p < 4; ++p) Bs[kkb + p * 4][ob] = bR[p];
        __syncthreads();

        // prefetch next tile into registers
        if (it + 1 < niter) {
            int koff = (it + 1) * 16;
            aR0 = *(const float4*)(aptr0 + koff);
            aR1 = *(const float4*)(aptr1 + koff);
#pragma unroll
            for (int p = 0; p < 4; ++p)
                bR[p] = g_W[(size_t)(k0 + koff + kkb + p * 4) * D_N + ob];
        }

        // compute 16 k-steps
#pragma unroll
        for (int kk = 0; kk < 16; ++kk) {
            float4 a0 = *(const float4*)&As[kk][mo0];
            float4 a1 = *(const float4*)&As[kk][mo1];
            float4 b  = *(const float4*)&Bs[kk][no];
            unsigned long long ap0 = pack2(a0.x, a0.y);
            unsigned long long ap1 = pack2(a0.z, a0.w);
            unsigned long long ap2 = pack2(a1.x, a1.y);
            unsigned long long ap3 = pack2(a1.z, a1.w);
            unsigned long long bb0 = pack2(b.x, b.x);
            unsigned long long bb1 = pack2(b.y, b.y);
            unsigned long long bb2 = pack2(b.z, b.z);
            unsigned long long bb3 = pack2(b.w, b.w);
            ffma2(acc[0][0], ap0, bb0); ffma2(acc[0][1], ap0, bb1);
            ffma2(acc[0][2], ap0, bb2); ffma2(acc[0][3], ap0, bb3);
            ffma2(acc[1][0], ap1, bb0); ffma2(acc[1][1], ap1, bb1);
            ffma2(acc[1][2], ap1, bb2); ffma2(acc[1][3], ap1, bb3);
            ffma2(acc[2][0], ap2, bb0); ffma2(acc[2][1], ap2, bb1);
            ffma2(acc[2][2], ap2, bb2); ffma2(acc[2][3], ap2, bb3);
            ffma2(acc[3][0], ap3, bb0); ffma2(acc[3][1], ap3, bb1);
            ffma2(acc[3][2], ap3, bb2); ffma2(acc[3][3], ap3, bb3);
        }
        __syncthreads();
    }

    // write partials (float4 per output row)
    float* outp = &g_part[s][0];
#pragma unroll
    for (int p = 0; p < 4; ++p) {
        int m = (p < 2) ? (mo0 + p * 2) : (mo1 + (p - 2) * 2);
        float lo[4], hi[4];
#pragma unroll
        for (int n = 0; n < 4; ++n) unpack2(acc[p][n], lo[n], hi[n]);
        *(float4*)&outp[(size_t)(mbase + m) * D_N + no] =
            make_float4(lo[0], lo[1], lo[2], lo[3]);
        *(float4*)&outp[(size_t)(mbase + m + 1) * D_N + no] =
            make_float4(hi[0], hi[1], hi[2], hi[3]);
    }
}

// ---------------------------------------------------------------------------
// Reduce split-K partials + epilogue (bond term [+ residual] + ReLU)
// osel: 0 -> g_xa, 1 -> g_xb, else external (d_out)
// ---------------------------------------------------------------------------
__global__ void reduce_kernel(const float* __restrict__ xres, int fi,
                              float* __restrict__ oext, int osel) {
    int i = blockIdx.x * blockDim.x + threadIdx.x;
    if (i >= A_N * D_N) return;
    float acc = g_bt[fi][i];
#pragma unroll
    for (int p = 0; p < NSPLIT; ++p) acc += g_part[p][i];
    if (xres) acc += xres[i];
    acc = fmaxf(acc, 0.f);
    float* out = (osel == 0) ? g_xa : (osel == 1) ? g_xb : oext;
    out[i] = acc;
}

// ---------------------------------------------------------------------------
// Launch: 4 conv stages (relu; +x relu) x 2 filters, each filter used twice
// ---------------------------------------------------------------------------
extern "C" void kernel_launch(void* const* d_in, const int* in_sizes, int n_in,
                              void* d_out, int out_size) {
    const float* x    = (const float*)d_in[0];   // (2048, 64)
    const float* conn = (const float*)d_in[1];   // (2048, 2048, 12)
    const float* bond = (const float*)d_in[2];   // (2048, 12, 2)
    const float* f0   = (const float*)d_in[3];   // (64, 12, 66)
    const float* f1   = (const float*)d_in[4];   // (64, 12, 66)
    float* out = (float*)d_out;

    prep_g_kernel<<<(2 * D_N * GN + 255) / 256, 256>>>(f0, f1);
    prep_bt_kernel<<<(2 * A_N * D_N + 255) / 256, 256>>>(bond, f0, f1);

    dim3 wgrid(32, 6);
    dim3 bgrid(16, NSPLIT);
    int rblocks = (A_N * D_N + 255) / 256;

    // stage 0: y = relu(conv(x, f0))                -> g_xa
    wgemm_kernel<<<wgrid, 256>>>(x, 2, 0);
    big_gemm_kernel<<<bgrid, 256>>>(conn);
    reduce_kernel<<<rblocks, 256>>>(nullptr, 0, nullptr, 0);

    // stage 1: y = relu(conv(y, f0) + x)            -> g_xb
    wgemm_kernel<<<wgrid, 256>>>(nullptr, 0, 0);
    big_gemm_kernel<<<bgrid, 256>>>(conn);
    reduce_kernel<<<rblocks, 256>>>(x, 0, nullptr, 1);

    // stage 2: y = relu(conv(y, f1))                -> g_xa
    wgemm_kernel<<<wgrid, 256>>>(nullptr, 1, 1);
    big_gemm_kernel<<<bgrid, 256>>>(conn);
    reduce_kernel<<<rblocks, 256>>>(nullptr, 1, nullptr, 0);

    // stage 3: y = relu(conv(y, f1) + x)            -> d_out
    wgemm_kernel<<<wgrid, 256>>>(nullptr, 0, 1);
    big_gemm_kernel<<<bgrid, 256>>>(conn);
    reduce_kernel<<<rblocks, 256>>>(x, 1, out, 2);
}

// round 9
// speedup vs baseline: 1.4749x; 1.4749x over previous
#include <cuda_runtime.h>
#include <cuda_bf16.h>

// Problem constants
#define A_N 2048
#define D_N 64
#define F_N 12
#define K_N (A_N * F_N)   // 24576
#define C_N 66            // D + 2
#define GN  (F_N * D_N)   // 768

// Split-K for the tensor GEMM: 16 M-tiles x 9 K-splits = 144 CTAs (one wave)
#define NSPLIT 9
#define KT_TOTAL 768          // 24576 / 32 K-tiles (BK=32)
#define KT_PER   86           // splits 0..7: 86 tiles, split 8: 80

// mma_gemm smem: 4 stages x 30720B (A rows padded to 80B for conflict-free ldmatrix)
#define ST_AH 0
#define ST_AL 10240
#define ST_BH 20480
#define ST_BL 25600
#define ST_SZ 30720
#define NSTG  4
#define TC_SMEM (NSTG * ST_SZ)   // 122880

// ---------------------------------------------------------------------------
// Scratch (device globals only — no allocation allowed)
// ---------------------------------------------------------------------------
__device__ __nv_bfloat16 g_ch[(size_t)A_N * K_N];   // conn hi (bf16)
__device__ __nv_bfloat16 g_cl[(size_t)A_N * K_N];   // conn lo (bf16 residual)
__device__ __nv_bfloat16 g_wth[(size_t)D_N * K_N];  // Wt hi: [o][k] K-major
__device__ __nv_bfloat16 g_wtl[(size_t)D_N * K_N];  // Wt lo: [o][k]
__device__ float g_G[2][D_N * GN];
__device__ float g_bt[2][A_N * D_N];
__device__ float g_W[K_N * D_N];                    // W[k][o] fp32 (wgemm out)
__device__ float g_xa[A_N * D_N];
__device__ float g_xb[A_N * D_N];
__device__ float g_part[NSPLIT][A_N * D_N];

// ---------------------------------------------------------------------------
// PTX helpers (all baseline sm_80-era: no arch-suffix-gated features)
// ---------------------------------------------------------------------------
__device__ __forceinline__ unsigned smem_u32(const void* p) {
    unsigned a;
    asm("{ .reg .u64 t; cvta.to.shared.u64 t, %1; cvt.u32.u64 %0, t; }"
        : "=r"(a) : "l"(p));
    return a;
}
__device__ __forceinline__ void cpasync16(unsigned dst, const void* src) {
    asm volatile("cp.async.cg.shared.global [%0], [%1], 16;"
                 :: "r"(dst), "l"(src) : "memory");
}
__device__ __forceinline__ void cp_commit() {
    asm volatile("cp.async.commit_group;" ::: "memory");
}
template <int N>
__device__ __forceinline__ void cp_wait() {
    asm volatile("cp.async.wait_group %0;" :: "n"(N) : "memory");
}
__device__ __forceinline__ void ldmx4(unsigned r[4], unsigned addr) {
    asm volatile("ldmatrix.sync.aligned.m8n8.x4.shared.b16 {%0,%1,%2,%3}, [%4];"
                 : "=r"(r[0]), "=r"(r[1]), "=r"(r[2]), "=r"(r[3]) : "r"(addr));
}
__device__ __forceinline__ void hmma(float c[4], const unsigned a[4],
                                     unsigned b0, unsigned b1) {
    asm volatile(
        "mma.sync.aligned.m16n8k16.row.col.f32.bf16.bf16.f32 "
        "{%0,%1,%2,%3}, {%4,%5,%6,%7}, {%8,%9}, {%0,%1,%2,%3};"
        : "+f"(c[0]), "+f"(c[1]), "+f"(c[2]), "+f"(c[3])
        : "r"(a[0]), "r"(a[1]), "r"(a[2]), "r"(a[3]), "r"(b0), "r"(b1));
}
__device__ __forceinline__ void split_bf16(float x, __nv_bfloat16& h, __nv_bfloat16& l) {
    h = __float2bfloat16_rn(x);
    l = __float2bfloat16_rn(x - __bfloat162float(h));
}

// ---------------------------------------------------------------------------
// One-time: conn fp32 -> (hi, lo) bf16 split
// ---------------------------------------------------------------------------
__global__ void __launch_bounds__(256) conv_split_kernel(const float* __restrict__ conn) {
    size_t i = (size_t)blockIdx.x * 256 + threadIdx.x;   // float4 index
    if (i >= (size_t)A_N * K_N / 4) return;
    float4 v = ((const float4*)conn)[i];
    __nv_bfloat16 h0, l0, h1, l1, h2, l2, h3, l3;
    split_bf16(v.x, h0, l0);
    split_bf16(v.y, h1, l1);
    split_bf16(v.z, h2, l2);
    split_bf16(v.w, h3, l3);
    union { __nv_bfloat16 b[4]; uint2 u; } ph, pl;
    ph.b[0] = h0; ph.b[1] = h1; ph.b[2] = h2; ph.b[3] = h3;
    pl.b[0] = l0; pl.b[1] = l1; pl.b[2] = l2; pl.b[3] = l3;
    ((uint2*)g_ch)[i] = ph.u;
    ((uint2*)g_cl)[i] = pl.u;
}

// ---------------------------------------------------------------------------
// Prep: transpose filters into G
// ---------------------------------------------------------------------------
__global__ void prep_g_kernel(const float* __restrict__ f0, const float* __restrict__ f1) {
    int i = blockIdx.x * blockDim.x + threadIdx.x;
    if (i >= 2 * D_N * GN) return;
    int fi = i / (D_N * GN);
    int r  = i % (D_N * GN);
    int d  = r / GN;
    int j  = r % GN;
    int f  = j >> 6;
    int o  = j & 63;
    const float* filt = fi ? f1 : f0;
    g_G[fi][r] = filt[(o * F_N + f) * C_N + d];
}

// Prep: bond term (x-independent)
__global__ void prep_bt_kernel(const float* __restrict__ bond,
                               const float* __restrict__ f0,
                               const float* __restrict__ f1) {
    int i = blockIdx.x * blockDim.x + threadIdx.x;
    if (i >= 2 * A_N * D_N) return;
    int fi = i / (A_N * D_N);
    int r  = i % (A_N * D_N);
    int a  = r / D_N;
    int o  = r % D_N;
    const float* filt = fi ? f1 : f0;
    float s = 0.f;
#pragma unroll
    for (int f = 0; f < F_N; ++f) {
        s += bond[(a * F_N + f) * 2 + 0] * filt[(o * F_N + f) * C_N + 64];
        s += bond[(a * F_N + f) * 2 + 1] * filt[(o * F_N + f) * C_N + 65];
    }
    g_bt[fi][r] = s;
}

// ---------------------------------------------------------------------------
// W GEMM:  W(2048 x 768) = X(2048 x 64) @ G(64 x 768)   (unchanged, proven)
// ---------------------------------------------------------------------------
__global__ void __launch_bounds__(256) wgemm_kernel(const float* __restrict__ xext,
                                                    int xsel, int fi) {
    const float* X = (xsel == 0) ? g_xa : (xsel == 1) ? g_xb : xext;
    const float* G = g_G[fi];

    __shared__ float xs[64][68];
    __shared__ float gs[64][128];

    int tid = threadIdx.x;
    int m0 = blockIdx.x * 64;
    int j0 = blockIdx.y * 128;

    for (int i = tid; i < 64 * 16; i += 256) {
        int row = i >> 4;
        int kq  = i & 15;
        float4 v = *(const float4*)&X[(size_t)(m0 + row) * D_N + kq * 4];
        xs[kq * 4 + 0][row] = v.x;
        xs[kq * 4 + 1][row] = v.y;
        xs[kq * 4 + 2][row] = v.z;
        xs[kq * 4 + 3][row] = v.w;
    }
    for (int i = tid; i < 64 * 32; i += 256) {
        int d  = i >> 5;
        int cq = i & 31;
        *(float4*)&gs[d][cq * 4] = *(const float4*)&G[(size_t)d * GN + j0 + cq * 4];
    }
    __syncthreads();

    int tx = tid & 31;
    int ty = tid >> 5;
    float acc[8][4];
#pragma unroll
    for (int im = 0; im < 8; ++im)
#pragma unroll
        for (int jn = 0; jn < 4; ++jn) acc[im][jn] = 0.f;

#pragma unroll 4
    for (int k = 0; k < 64; ++k) {
        float4 a0 = *(const float4*)&xs[k][ty * 8];
        float4 a1 = *(const float4*)&xs[k][ty * 8 + 4];
        float4 b  = *(const float4*)&gs[k][tx * 4];
        float av[8] = {a0.x, a0.y, a0.z, a0.w, a1.x, a1.y, a1.z, a1.w};
        float bv[4] = {b.x, b.y, b.z, b.w};
#pragma unroll
        for (int im = 0; im < 8; ++im)
#pragma unroll
            for (int jn = 0; jn < 4; ++jn) acc[im][jn] += av[im] * bv[jn];
    }

#pragma unroll
    for (int im = 0; im < 8; ++im) {
        size_t row = (size_t)(m0 + ty * 8 + im);
        *(float4*)&g_W[row * GN + j0 + tx * 4] =
            make_float4(acc[im][0], acc[im][1], acc[im][2], acc[im][3]);
    }
}

// ---------------------------------------------------------------------------
// Transpose+split W[k][o] fp32 -> Wt_hi/lo[o][k] bf16   (grid 384, 256 thr)
// ---------------------------------------------------------------------------
__global__ void __launch_bounds__(256) wtsplit_kernel() {
    __shared__ float ws[64][65];
    int kb = blockIdx.x * 64;
    int tid = threadIdx.x;
    for (int i = tid; i < 1024; i += 256) {
        int k = i >> 4, oq = i & 15;
        float4 v = *(const float4*)&g_W[(size_t)(kb + k) * D_N + oq * 4];
        ws[k][oq * 4 + 0] = v.x;
        ws[k][oq * 4 + 1] = v.y;
        ws[k][oq * 4 + 2] = v.z;
        ws[k][oq * 4 + 3] = v.w;
    }
    __syncthreads();
    for (int i = tid; i < 4096; i += 256) {
        int o = i >> 6, k = i & 63;
        __nv_bfloat16 h, l;
        split_bf16(ws[k][o], h, l);
        g_wth[(size_t)o * K_N + kb + k] = h;
        g_wtl[(size_t)o * K_N + kb + k] = l;
    }
}

// ---------------------------------------------------------------------------
// Tensor GEMM via warp-level mma.sync (split-bf16, 3 terms, split-K):
//   part[s][a][o] = sum_k conn[a][k] * W[k][o] over this split's K range
// grid (16, 9), 256 threads = 8 warps (4 M x 2 N), warp tile 32x32, BK=32.
// 4-stage cp.async pipeline, 3 tiles in flight.
// ---------------------------------------------------------------------------
__global__ void __launch_bounds__(256, 1) mma_gemm_kernel() {
    extern __shared__ char smem[];
    unsigned sb = smem_u32(smem);
    int tid  = threadIdx.x;
    int lane = tid & 31;
    int wid  = tid >> 5;
    int wm   = wid & 3;          // warp M index (32 rows each)
    int wn   = wid >> 2;         // warp N index (32 cols each)
    int mbase = blockIdx.x * 128;
    int s     = blockIdx.y;
    int kt0   = s * KT_PER;
    int nkt   = (s < 8) ? KT_PER : (KT_TOTAL - 8 * KT_PER);

    // ldmatrix lane-address offsets (bytes, within a stage region)
    // A (16x16 tile, x4): lanes 0-15 -> rows 0-15 @k0; lanes 16-31 -> rows @k0+8
    int a_row = lane & 15;
    int a_kad = (lane >> 4) * 8;
    unsigned aoff = (unsigned)((wm * 32 + a_row) * 80 + a_kad * 2);
    // B (n16 x k16, x4): groups of 8 lanes -> (n0-7,k0),(n0-7,k8),(n8-15,k0),(n8-15,k8)
    int bg  = lane >> 3;
    int b_n = (bg >> 1) * 8 + (lane & 7);
    int b_k = (bg & 1) * 8;
    unsigned boff = (unsigned)((wn * 32 + b_n) * 80 + b_k * 2);

    float c[2][4][4];
#pragma unroll
    for (int mf = 0; mf < 2; ++mf)
#pragma unroll
        for (int nf = 0; nf < 4; ++nf)
#pragma unroll
            for (int q = 0; q < 4; ++q) c[mf][nf][q] = 0.f;

    auto load_tile = [&](int t) {
        unsigned stg = sb + (unsigned)(t & 3) * ST_SZ;
        size_t kk = (size_t)(kt0 + t) * 32;
        // A: 1024 x 16B chunks (hi 512 + lo 512), 4 per thread
#pragma unroll
        for (int j = 0; j < 4; ++j) {
            int i  = j * 256 + tid;
            int hi = i >> 9;
            int r  = (i >> 2) & 127;
            int cc = i & 3;
            const __nv_bfloat16* src =
                (hi ? g_cl : g_ch) + (size_t)(mbase + r) * K_N + kk + cc * 8;
            cpasync16(stg + (hi ? ST_AL : ST_AH) + (unsigned)(r * 80 + cc * 16), src);
        }
        // B: 512 chunks (hi 256 + lo 256), 2 per thread
#pragma unroll
        for (int j = 0; j < 2; ++j) {
            int i  = j * 256 + tid;
            int hi = i >> 8;
            int r  = (i >> 2) & 63;
            int cc = i & 3;
            const __nv_bfloat16* src =
                (hi ? g_wtl : g_wth) + (size_t)r * K_N + kk + cc * 8;
            cpasync16(stg + (hi ? ST_BL : ST_BH) + (unsigned)(r * 80 + cc * 16), src);
        }
    };

    // prologue: 3 tiles in flight (nkt >= 80)
#pragma unroll
    for (int t = 0; t < 3; ++t) {
        load_tile(t);
        cp_commit();
    }

    for (int kt = 0; kt < nkt; ++kt) {
        cp_wait<2>();          // tile kt's group complete (<=2 newest pending)
        __syncthreads();       // all warps past stage (kt-1)&3 compute

        // issue next loads first (into stage (kt+3)&3 == (kt-1)&3, safe post-sync)
        if (kt + 3 < nkt) load_tile(kt + 3);
        cp_commit();           // exactly one group per iteration

        unsigned stg = sb + (unsigned)(kt & 3) * ST_SZ;
#pragma unroll
        for (int ks = 0; ks < 2; ++ks) {
            unsigned kof = (unsigned)(ks * 32);   // 16 elems * 2B
            unsigned ah[2][4], al[2][4], bH[2][4], bL[2][4];
#pragma unroll
            for (int mf = 0; mf < 2; ++mf)
                ldmx4(ah[mf], stg + ST_AH + aoff + mf * 1280 + kof);
#pragma unroll
            for (int mf = 0; mf < 2; ++mf)
                ldmx4(al[mf], stg + ST_AL + aoff + mf * 1280 + kof);
#pragma unroll
            for (int nf2 = 0; nf2 < 2; ++nf2)
                ldmx4(bH[nf2], stg + ST_BH + boff + nf2 * 1280 + kof);
#pragma unroll
            for (int nf2 = 0; nf2 < 2; ++nf2)
                ldmx4(bL[nf2], stg + ST_BL + boff + nf2 * 1280 + kof);
#pragma unroll
            for (int mf = 0; mf < 2; ++mf)
#pragma unroll
                for (int nf = 0; nf < 4; ++nf) {
                    unsigned b0h = bH[nf >> 1][(nf & 1) * 2 + 0];
                    unsigned b1h = bH[nf >> 1][(nf & 1) * 2 + 1];
                    unsigned b0l = bL[nf >> 1][(nf & 1) * 2 + 0];
                    unsigned b1l = bL[nf >> 1][(nf & 1) * 2 + 1];
                    hmma(c[mf][nf], ah[mf], b0h, b1h);   // hi*hi
                    hmma(c[mf][nf], al[mf], b0h, b1h);   // lo*hi
                    hmma(c[mf][nf], ah[mf], b0l, b1l);   // hi*lo
                }
        }
    }

    // epilogue: write split-K partials (deterministic buffers)
    float* op = &g_part[s][0];
#pragma unroll
    for (int mf = 0; mf < 2; ++mf)
#pragma unroll
        for (int nf = 0; nf < 4; ++nf) {
            int r0  = mbase + wm * 32 + mf * 16 + (lane >> 2);
            int col = wn * 32 + nf * 8 + (lane & 3) * 2;
            *(float2*)&op[(size_t)r0 * D_N + col] =
                make_float2(c[mf][nf][0], c[mf][nf][1]);
            *(float2*)&op[(size_t)(r0 + 8) * D_N + col] =
                make_float2(c[mf][nf][2], c[mf][nf][3]);
        }
}

// ---------------------------------------------------------------------------
// Reduce split-K partials + epilogue (bond term [+ residual] + ReLU)
// ---------------------------------------------------------------------------
__global__ void reduce_kernel(const float* __restrict__ xres, int fi,
                              float* __restrict__ oext, int osel) {
    int i = blockIdx.x * blockDim.x + threadIdx.x;
    if (i >= A_N * D_N) return;
    float acc = g_bt[fi][i];
#pragma unroll
    for (int p = 0; p < NSPLIT; ++p) acc += g_part[p][i];
    if (xres) acc += xres[i];
    acc = fmaxf(acc, 0.f);
    float* out = (osel == 0) ? g_xa : (osel == 1) ? g_xb : oext;
    out[i] = acc;
}

// ---------------------------------------------------------------------------
// Launch: 4 conv stages (relu; +x relu) x 2 filters, each filter used twice
// ---------------------------------------------------------------------------
extern "C" void kernel_launch(void* const* d_in, const int* in_sizes, int n_in,
                              void* d_out, int out_size) {
    const float* x    = (const float*)d_in[0];   // (2048, 64)
    const float* conn = (const float*)d_in[1];   // (2048, 2048, 12)
    const float* bond = (const float*)d_in[2];   // (2048, 12, 2)
    const float* f0   = (const float*)d_in[3];   // (64, 12, 66)
    const float* f1   = (const float*)d_in[4];   // (64, 12, 66)
    float* out = (float*)d_out;

    cudaFuncSetAttribute(mma_gemm_kernel,
                         cudaFuncAttributeMaxDynamicSharedMemorySize, TC_SMEM);

    prep_g_kernel<<<(2 * D_N * GN + 255) / 256, 256>>>(f0, f1);
    prep_bt_kernel<<<(2 * A_N * D_N + 255) / 256, 256>>>(bond, f0, f1);

    // one-time split of conn into hi/lo bf16 (reused by all 4 stages)
    size_t nvec = (size_t)A_N * K_N / 4;
    conv_split_kernel<<<(unsigned)((nvec + 255) / 256), 256>>>(conn);

    dim3 wgrid(32, 6);
    dim3 tgrid(16, NSPLIT);
    int rblocks = (A_N * D_N + 255) / 256;

    // stage 0: y = relu(conv(x, f0))                -> g_xa
    wgemm_kernel<<<wgrid, 256>>>(x, 2, 0);
    wtsplit_kernel<<<KT_TOTAL / 2, 256>>>();
    mma_gemm_kernel<<<tgrid, 256, TC_SMEM>>>();
    reduce_kernel<<<rblocks, 256>>>(nullptr, 0, nullptr, 0);

    // stage 1: y = relu(conv(y, f0) + x)            -> g_xb
    wgemm_kernel<<<wgrid, 256>>>(nullptr, 0, 0);
    wtsplit_kernel<<<KT_TOTAL / 2, 256>>>();
    mma_gemm_kernel<<<tgrid, 256, TC_SMEM>>>();
    reduce_kernel<<<rblocks, 256>>>(x, 0, nullptr, 1);

    // stage 2: y = relu(conv(y, f1))                -> g_xa
    wgemm_kernel<<<wgrid, 256>>>(nullptr, 1, 1);
    wtsplit_kernel<<<KT_TOTAL / 2, 256>>>();
    mma_gemm_kernel<<<tgrid, 256, TC_SMEM>>>();
    reduce_kernel<<<rblocks, 256>>>(nullptr, 1, nullptr, 0);

    // stage 3: y = relu(conv(y, f1) + x)            -> d_out
    wgemm_kernel<<<wgrid, 256>>>(nullptr, 0, 1);
    wtsplit_kernel<<<KT_TOTAL / 2, 256>>>();
    mma_gemm_kernel<<<tgrid, 256, TC_SMEM>>>();
    reduce_kernel<<<rblocks, 256>>>(x, 1, out, 2);
}